// round 1
// baseline (speedup 1.0000x reference)
#include <cuda_runtime.h>
#include <math.h>
#include <stddef.h>

#define SEQ   4096
#define INP   2048
#define HID   2048
#define G3    6144
#define NBLK  128
#define NTHR  1024

// ---------------- device globals (no allocations allowed) ----------------
__device__ float g_igates[(size_t)SEQ * G3];   // 100.7 MB scratch
__device__ float g_h[2][HID];                  // double-buffered hidden state
__device__ unsigned g_cnt;
__device__ volatile unsigned g_gen;

// ---------------- init: reset barrier, seed h(0) ----------------
__global__ void init_k(const float* __restrict__ init_state) {
    int i = blockIdx.x * blockDim.x + threadIdx.x;
    if (i < HID) g_h[0][i] = init_state[i];
    if (i == 0) { g_cnt = 0u; g_gen = 0u; }
}

// ---------------- igates GEMM: C[m][n] = xs[m,:] . Wi[n,:] + bi[n] ----------------
// M=4096, N=6144, K=2048. Block tile 128x128, k-tile 16, 256 threads, 8x8/thread.
#define BM 128
#define BN 128
#define BK 16
__global__ __launch_bounds__(256) void gemm_k(const float* __restrict__ xs,
                                              const float* __restrict__ Wi,
                                              const float* __restrict__ bi) {
    __shared__ float As[BK][BM];
    __shared__ float Bs[BK][BN];
    const int tx = threadIdx.x & 15;
    const int ty = threadIdx.x >> 4;
    const int m0 = blockIdx.y * BM;
    const int n0 = blockIdx.x * BN;

    float acc[8][8];
#pragma unroll
    for (int i = 0; i < 8; i++)
#pragma unroll
        for (int j = 0; j < 8; j++) acc[i][j] = 0.f;

    for (int k0 = 0; k0 < INP; k0 += BK) {
#pragma unroll
        for (int i = 0; i < 2; i++) {
            int a  = threadIdx.x * 2 + i;   // 0..511
            int m  = a >> 2;
            int kc = (a & 3) * 4;
            float4 v = *(const float4*)&xs[(size_t)(m0 + m) * INP + k0 + kc];
            As[kc + 0][m] = v.x; As[kc + 1][m] = v.y; As[kc + 2][m] = v.z; As[kc + 3][m] = v.w;
            float4 w = *(const float4*)&Wi[(size_t)(n0 + m) * INP + k0 + kc];
            Bs[kc + 0][m] = w.x; Bs[kc + 1][m] = w.y; Bs[kc + 2][m] = w.z; Bs[kc + 3][m] = w.w;
        }
        __syncthreads();
#pragma unroll
        for (int kk = 0; kk < BK; kk++) {
            float a[8], b[8];
            *(float4*)&a[0] = *(const float4*)&As[kk][ty * 4];
            *(float4*)&a[4] = *(const float4*)&As[kk][64 + ty * 4];
            *(float4*)&b[0] = *(const float4*)&Bs[kk][tx * 4];
            *(float4*)&b[4] = *(const float4*)&Bs[kk][64 + tx * 4];
#pragma unroll
            for (int i = 0; i < 8; i++)
#pragma unroll
                for (int j = 0; j < 8; j++) acc[i][j] = fmaf(a[i], b[j], acc[i][j]);
        }
        __syncthreads();
    }

    float4 bia = *(const float4*)&bi[n0 + tx * 4];
    float4 bib = *(const float4*)&bi[n0 + 64 + tx * 4];
#pragma unroll
    for (int i = 0; i < 8; i++) {
        int m = m0 + ((i < 4) ? (ty * 4 + i) : (64 + ty * 4 + (i - 4)));
        float4 v0, v1;
        v0.x = acc[i][0] + bia.x; v0.y = acc[i][1] + bia.y;
        v0.z = acc[i][2] + bia.z; v0.w = acc[i][3] + bia.w;
        v1.x = acc[i][4] + bib.x; v1.y = acc[i][5] + bib.y;
        v1.z = acc[i][6] + bib.z; v1.w = acc[i][7] + bib.w;
        *(float4*)&g_igates[(size_t)m * G3 + n0 + tx * 4]      = v0;
        *(float4*)&g_igates[(size_t)m * G3 + n0 + 64 + tx * 4] = v1;
    }
}

// ---------------- persistent GRU recurrence ----------------
// 128 blocks x 1024 threads, 1 block/SM (forced by 222KB smem) -> spin barrier safe.
// Block b owns hidden units j = b*16 .. b*16+15. Unit u <-> 64 threads (2 warps).
// Lane l (0..63) owns k-slice [l*32, l*32+32). Per lane:
//   n-gate row weights (32 fp32) + first 12 of z-gate -> registers (44 regs)
//   rest of z (20) + full r row (32) -> smem, 13 float4 per lane (odd stride: conflict-free)
#define SMEM_WS_F4   13312                 // 1024 lanes * 13 f4
#define SMEM_H_F4    576                   // 512 f4 padded with stride 9 per 8
#define SMEM_BYTES   ((SMEM_WS_F4 + SMEM_H_F4) * 16 + 32 * 4 * 4)

__device__ __forceinline__ float dot4(float4 a, float4 b) {
    return fmaf(a.x, b.x, fmaf(a.y, b.y, fmaf(a.z, b.z, a.w * b.w)));
}

__global__ __launch_bounds__(NTHR, 1) void gru_k(const float* __restrict__ Wh,
                                                 const float* __restrict__ bn,
                                                 float* __restrict__ out,
                                                 int out_size) {
    extern __shared__ float4 sm4[];
    float4* ws  = sm4;                       // weights
    float4* h4  = sm4 + SMEM_WS_F4;          // padded h
    float*  red = (float*)(sm4 + SMEM_WS_F4 + SMEM_H_F4);  // 32 warps * 4

    const int tid = threadIdx.x;
    const int u   = tid >> 6;
    const int l   = tid & 63;
    const int b   = blockIdx.x;
    const int j   = b * 16 + u;
    const int k0  = l * 32;

    // ---- preload weights ----
    const float4* nrow = (const float4*)(Wh + (size_t)(4096 + j) * HID + k0);
    const float4* zrow = (const float4*)(Wh + (size_t)(2048 + j) * HID + k0);
    const float4* rrow = (const float4*)(Wh + (size_t)(j)        * HID + k0);
    float4 wn[8], wz[3];
#pragma unroll
    for (int i = 0; i < 8; i++) wn[i] = nrow[i];
#pragma unroll
    for (int i = 0; i < 3; i++) wz[i] = zrow[i];
    float4* wsl = ws + tid * 13;
#pragma unroll
    for (int i = 0; i < 5; i++) wsl[i] = zrow[3 + i];
#pragma unroll
    for (int i = 0; i < 8; i++) wsl[5 + i] = rrow[i];

    const bool leader = (l == 0);
    const float bnj = leader ? bn[j] : 0.f;
    const bool write_last = (out_size >= SEQ * HID + HID);
    __syncthreads();

    for (int t = 0; t < SEQ; t++) {
        const int cur = t & 1;

        // leader: issue igate loads early (latency hidden under dot phase)
        float igR = 0.f, igZ = 0.f, igN = 0.f;
        if (leader) {
            const float* ig = g_igates + (size_t)t * G3 + j;
            igR = __ldg(ig);
            igZ = __ldg(ig + 2048);
            igN = __ldg(ig + 4096);
        }

        // cooperative broadcast of h(t) -> smem (must bypass L1: written by other SMs)
        if (tid < 512) {
            float4 hv = __ldcg((const float4*)g_h[cur] + tid);
            h4[(tid >> 3) * 9 + (tid & 7)] = hv;
        }
        __syncthreads();

        // partial dot products
        float accR = 0.f, accZ = 0.f, accN = 0.f;
        const float4* hp = h4 + l * 9;
#pragma unroll
        for (int i = 0; i < 8; i++) {
            float4 hv = hp[i];
            accN = fmaf(1.f, dot4(wn[i], hv), accN);
            float4 c = (i < 3) ? wz[i] : wsl[i - 3];
            accZ += dot4(c, hv);
            accR += dot4(wsl[5 + i], hv);
        }

        // warp reduce (3 values)
#pragma unroll
        for (int o = 16; o > 0; o >>= 1) {
            accR += __shfl_down_sync(0xffffffffu, accR, o);
            accZ += __shfl_down_sync(0xffffffffu, accZ, o);
            accN += __shfl_down_sync(0xffffffffu, accN, o);
        }
        const int w = tid >> 5;
        if ((tid & 31) == 0) {
            red[w * 4 + 0] = accR;
            red[w * 4 + 1] = accZ;
            red[w * 4 + 2] = accN;
        }
        __syncthreads();

        if (leader) {
            float hr = red[(2 * u) * 4 + 0] + red[(2 * u + 1) * 4 + 0];
            float hz = red[(2 * u) * 4 + 1] + red[(2 * u + 1) * 4 + 1];
            float hn = red[(2 * u) * 4 + 2] + red[(2 * u + 1) * 4 + 2];
            int q = j >> 2;
            float hold = ((const float*)&h4[(q >> 3) * 9 + (q & 7)])[j & 3];
            float r = 1.f / (1.f + expf(-(igR + hr)));
            float z = 1.f / (1.f + expf(-(igZ + hz)));
            float nn = tanhf(igN + r * (hn + bnj));
            float hnew = (1.f - z) * nn + z * hold;
            __stcg(&g_h[cur ^ 1][j], hnew);
            out[(size_t)t * HID + j] = hnew;
            if (t == SEQ - 1 && write_last) out[(size_t)SEQ * HID + j] = hnew;
            __threadfence();
        }
        __syncthreads();

        // grid barrier (generation counter, all 128 blocks resident)
        if (tid == 0) {
            unsigned old = atomicAdd(&g_cnt, 1u);
            if (old == NBLK - 1) {
                *(volatile unsigned*)&g_cnt = 0u;
                __threadfence();
                g_gen = (unsigned)(t + 1);
            } else {
                while (g_gen < (unsigned)(t + 1)) { }
                __threadfence();
            }
        }
        __syncthreads();
    }
}

// ---------------- launch ----------------
extern "C" void kernel_launch(void* const* d_in, const int* in_sizes, int n_in,
                              void* d_out, int out_size) {
    const float* xs         = (const float*)d_in[0];
    const float* init_state = (const float*)d_in[1];
    const float* Wi         = (const float*)d_in[2];
    const float* Wh         = (const float*)d_in[3];
    const float* bi         = (const float*)d_in[4];
    const float* bn         = (const float*)d_in[5];
    float* out = (float*)d_out;

    cudaFuncSetAttribute(gru_k, cudaFuncAttributeMaxDynamicSharedMemorySize, SMEM_BYTES);

    init_k<<<8, 256>>>(init_state);
    dim3 gg(G3 / BN, SEQ / BM);
    gemm_k<<<gg, 256>>>(xs, Wi, bi);
    gru_k<<<NBLK, NTHR, SMEM_BYTES>>>(Wh, bn, out, out_size);
}

// round 3
// speedup vs baseline: 1.2595x; 1.2595x over previous
#include <cuda_runtime.h>
#include <math.h>
#include <stddef.h>

#define SEQ   4096
#define INP   2048
#define HID   2048
#define G3    6144
#define NBLK  128
#define NTHR  512

// ---------------- device globals (no allocations allowed) ----------------
__device__ float g_igates[(size_t)SEQ * G3];   // 100.7 MB scratch
__device__ float g_h[2][HID];                  // double-buffered hidden state
__device__ unsigned g_flags[NBLK * 32];        // per-block progress flags, 128B stride

__device__ __forceinline__ unsigned ld_acquire(const unsigned* p) {
    unsigned v;
    asm volatile("ld.acquire.gpu.global.u32 %0, [%1];" : "=r"(v) : "l"(p) : "memory");
    return v;
}
__device__ __forceinline__ void st_release(unsigned* p, unsigned v) {
    asm volatile("st.release.gpu.global.u32 [%0], %1;" :: "l"(p), "r"(v) : "memory");
}

// ---------------- init: reset flags, seed h(0) ----------------
__global__ void init_k(const float* __restrict__ init_state) {
    int i = blockIdx.x * blockDim.x + threadIdx.x;
    if (i < HID) {
        g_h[0][i] = init_state[i];
        g_h[1][i] = 0.f;
    }
    if (i < NBLK * 32) g_flags[i] = 0u;
}

// ---------------- igates GEMM: C[m][n] = xs[m,:] . Wi[n,:] + bi[n] ----------------
#define BM 128
#define BN 128
#define BK 16
__global__ __launch_bounds__(256) void gemm_k(const float* __restrict__ xs,
                                              const float* __restrict__ Wi,
                                              const float* __restrict__ bi) {
    __shared__ float As[BK][BM];
    __shared__ float Bs[BK][BN];
    const int tx = threadIdx.x & 15;
    const int ty = threadIdx.x >> 4;
    const int m0 = blockIdx.y * BM;
    const int n0 = blockIdx.x * BN;

    float acc[8][8];
#pragma unroll
    for (int i = 0; i < 8; i++)
#pragma unroll
        for (int j = 0; j < 8; j++) acc[i][j] = 0.f;

    for (int k0 = 0; k0 < INP; k0 += BK) {
#pragma unroll
        for (int i = 0; i < 2; i++) {
            int a  = threadIdx.x * 2 + i;   // 0..511
            int m  = a >> 2;
            int kc = (a & 3) * 4;
            float4 v = *(const float4*)&xs[(size_t)(m0 + m) * INP + k0 + kc];
            As[kc + 0][m] = v.x; As[kc + 1][m] = v.y; As[kc + 2][m] = v.z; As[kc + 3][m] = v.w;
            float4 w = *(const float4*)&Wi[(size_t)(n0 + m) * INP + k0 + kc];
            Bs[kc + 0][m] = w.x; Bs[kc + 1][m] = w.y; Bs[kc + 2][m] = w.z; Bs[kc + 3][m] = w.w;
        }
        __syncthreads();
#pragma unroll
        for (int kk = 0; kk < BK; kk++) {
            float a[8], b[8];
            *(float4*)&a[0] = *(const float4*)&As[kk][ty * 4];
            *(float4*)&a[4] = *(const float4*)&As[kk][64 + ty * 4];
            *(float4*)&b[0] = *(const float4*)&Bs[kk][tx * 4];
            *(float4*)&b[4] = *(const float4*)&Bs[kk][64 + tx * 4];
#pragma unroll
            for (int i = 0; i < 8; i++)
#pragma unroll
                for (int j = 0; j < 8; j++) acc[i][j] = fmaf(a[i], b[j], acc[i][j]);
        }
        __syncthreads();
    }

    float4 bia = *(const float4*)&bi[n0 + tx * 4];
    float4 bib = *(const float4*)&bi[n0 + 64 + tx * 4];
#pragma unroll
    for (int i = 0; i < 8; i++) {
        int m = m0 + ((i < 4) ? (ty * 4 + i) : (64 + ty * 4 + (i - 4)));
        float4 v0, v1;
        v0.x = acc[i][0] + bia.x; v0.y = acc[i][1] + bia.y;
        v0.z = acc[i][2] + bia.z; v0.w = acc[i][3] + bia.w;
        v1.x = acc[i][4] + bib.x; v1.y = acc[i][5] + bib.y;
        v1.z = acc[i][6] + bib.z; v1.w = acc[i][7] + bib.w;
        *(float4*)&g_igates[(size_t)m * G3 + n0 + tx * 4]      = v0;
        *(float4*)&g_igates[(size_t)m * G3 + n0 + 64 + tx * 4] = v1;
    }
}

// ---------------- persistent GRU recurrence ----------------
// 128 blocks x 512 threads, 1 block/SM (213KB smem). Block b owns hidden units
// j = b*16..b*16+15; unit u = warp u. Lane l owns k-slice [64l, 64l+64).
// Per lane: n-row (16 f4) + z-row head (7 f4) in REGISTERS (92 regs of 128 cap);
// z tail (9 f4) + r row (16 f4) in SMEM at stride 25 f4/lane (conflict-free:
// within an 8-lane LDS.128 phase banks are 4l mod 32, distinct).
// h in SMEM padded 17 f4 per 16-f4 chunk (same conflict-free structure).
// Cross-SM sync: per-block release/acquire flags, no central atomic.
#define WS_F4   (NTHR * 25)   // 12800
#define H_F4    544           // 32 chunks * 17
#define ST_F4   4
#define SMEM_BYTES ((WS_F4 + H_F4 + ST_F4) * 16)

__global__ __launch_bounds__(NTHR, 1) void gru_k(const float* __restrict__ Wh,
                                                 const float* __restrict__ bn,
                                                 float* __restrict__ out,
                                                 int out_size) {
    extern __shared__ float4 sm4[];
    float4* ws  = sm4;                 // weights
    float4* h4p = sm4 + WS_F4;         // padded h
    float*  sth = (float*)(sm4 + WS_F4 + H_F4);  // 16 staged hnew

    const int tid = threadIdx.x;
    const int u   = tid >> 5;
    const int l   = tid & 31;
    const int b   = blockIdx.x;
    const int j   = b * 16 + u;
    const int k0  = l * 64;

    // ---- preload weights ----
    const float4* nrow = (const float4*)(Wh + (size_t)(4096 + j) * HID + k0);
    const float4* zrow = (const float4*)(Wh + (size_t)(2048 + j) * HID + k0);
    const float4* rrow = (const float4*)(Wh + (size_t)(j)        * HID + k0);
    float4 wn[16], wz[7];
#pragma unroll
    for (int i = 0; i < 16; i++) wn[i] = nrow[i];
#pragma unroll
    for (int i = 0; i < 7; i++)  wz[i] = zrow[i];
    float4* wsl = ws + tid * 25;
#pragma unroll
    for (int i = 0; i < 9; i++)  wsl[i] = zrow[7 + i];
#pragma unroll
    for (int i = 0; i < 16; i++) wsl[9 + i] = rrow[i];

    const bool leader = (l == 0);
    const float bnj = leader ? bn[j] : 0.f;
    const bool write_last = (out_size >= SEQ * HID + HID);
    __syncthreads();

    for (int t = 0; t < SEQ; t++) {
        const int buf = t & 1, nxt = buf ^ 1;

        // igate prefetch (no h dependency -> issues before/under the poll)
        float igR = 0.f, igZ = 0.f, igN = 0.f;
        if (leader) {
            const float* ig = g_igates + (size_t)t * G3 + j;
            igR = __ldg(ig);
            igZ = __ldg(ig + 2048);
            igN = __ldg(ig + 4096);
        }

        // fused acquire-poll + h broadcast: thread s<128 imports block s's 16 h values
        if (tid < NBLK) {
            if (t > 0) {
                const unsigned* fp = &g_flags[tid * 32];
                while (ld_acquire(fp) < (unsigned)t) { }
            }
            const float4* src = (const float4*)g_h[buf] + tid * 4;
#pragma unroll
            for (int i = 0; i < 4; i++) {
                float4 v = __ldcg(src + i);
                int q = tid * 4 + i;
                h4p[17 * (q >> 4) + (q & 15)] = v;
            }
        }
        __syncthreads();

        // partial dot products (all traffic register/LDS, conflict-free)
        float accR = 0.f, accZ = 0.f, accN = 0.f;
        const float4* hp = h4p + 17 * l;
#pragma unroll
        for (int i = 0; i < 16; i++) {
            float4 hv = hp[i];
            accN = fmaf(wn[i].x, hv.x, fmaf(wn[i].y, hv.y, fmaf(wn[i].z, hv.z, fmaf(wn[i].w, hv.w, accN))));
            float4 zc = (i < 7) ? wz[i] : wsl[i - 7];
            accZ = fmaf(zc.x, hv.x, fmaf(zc.y, hv.y, fmaf(zc.z, hv.z, fmaf(zc.w, hv.w, accZ))));
            float4 rc = wsl[9 + i];
            accR = fmaf(rc.x, hv.x, fmaf(rc.y, hv.y, fmaf(rc.z, hv.z, fmaf(rc.w, hv.w, accR))));
        }

        // warp reduce
#pragma unroll
        for (int o = 16; o > 0; o >>= 1) {
            accR += __shfl_down_sync(0xffffffffu, accR, o);
            accZ += __shfl_down_sync(0xffffffffu, accZ, o);
            accN += __shfl_down_sync(0xffffffffu, accN, o);
        }

        if (leader) {
            int q = j >> 2;
            float hold = ((const float*)&h4p[17 * (q >> 4) + (q & 15)])[j & 3];
            float r  = 1.f / (1.f + __expf(-(igR + accR)));
            float z  = 1.f / (1.f + __expf(-(igZ + accZ)));
            float nn = tanhf(igN + r * (accN + bnj));
            sth[u] = (1.f - z) * nn + z * hold;
        }
        __syncthreads();

        // publish: ONE thread writes this block's 16 h values then releases flag
        if (tid == 0) {
            float4 v0 = *(float4*)&sth[0];
            float4 v1 = *(float4*)&sth[4];
            float4 v2 = *(float4*)&sth[8];
            float4 v3 = *(float4*)&sth[12];
            float4* dst = (float4*)&g_h[nxt][b * 16];
            __stcg(dst + 0, v0); __stcg(dst + 1, v1);
            __stcg(dst + 2, v2); __stcg(dst + 3, v3);
            st_release(&g_flags[b * 32], (unsigned)(t + 1));
        }
        // coalesced 64B output-row write
        if (tid < 4) {
            *(float4*)&out[(size_t)t * HID + b * 16 + tid * 4] = *(float4*)&sth[tid * 4];
            if (t == SEQ - 1 && write_last)
                *(float4*)&out[(size_t)SEQ * HID + b * 16 + tid * 4] = *(float4*)&sth[tid * 4];
        }
    }
}

// ---------------- launch ----------------
extern "C" void kernel_launch(void* const* d_in, const int* in_sizes, int n_in,
                              void* d_out, int out_size) {
    const float* xs         = (const float*)d_in[0];
    const float* init_state = (const float*)d_in[1];
    const float* Wi         = (const float*)d_in[2];
    const float* Wh         = (const float*)d_in[3];
    const float* bi         = (const float*)d_in[4];
    const float* bn         = (const float*)d_in[5];
    float* out = (float*)d_out;

    cudaFuncSetAttribute(gru_k, cudaFuncAttributeMaxDynamicSharedMemorySize, SMEM_BYTES);

    init_k<<<16, 256>>>(init_state);
    dim3 gg(G3 / BN, SEQ / BM);
    gemm_k<<<gg, 256>>>(xs, Wi, bi);
    gru_k<<<NBLK, NTHR, SMEM_BYTES>>>(Wh, bn, out, out_size);
}